// round 7
// baseline (speedup 1.0000x reference)
#include <cuda_runtime.h>
#include <cstdint>

#define Bn 32
#define Hn 56
#define Wn 56
#define Cn 256
#define RS (Wn * Cn)

typedef unsigned long long ull;
typedef unsigned int u32;

// ---- packed f32x2 helpers (Blackwell FFMA2 path: only reachable via PTX) ----
__device__ __forceinline__ ull fma2(ull a, ull b, ull c) {
    ull d; asm("fma.rn.f32x2 %0, %1, %2, %3;" : "=l"(d) : "l"(a), "l"(b), "l"(c)); return d;
}
__device__ __forceinline__ ull mul2(ull a, ull b) {
    ull d; asm("mul.rn.f32x2 %0, %1, %2;" : "=l"(d) : "l"(a), "l"(b)); return d;
}
__device__ __forceinline__ ull add2(ull a, ull b) {
    ull d; asm("add.rn.f32x2 %0, %1, %2;" : "=l"(d) : "l"(a), "l"(b)); return d;
}
__device__ __forceinline__ ull pk2(u32 lo, u32 hi) {
    ull d; asm("mov.b64 %0, {%1, %2};" : "=l"(d) : "r"(lo), "r"(hi)); return d;
}
__device__ __forceinline__ void up2(ull v, u32 &lo, u32 &hi) {
    asm("mov.b64 {%0, %1}, %2;" : "=r"(lo), "=r"(hi) : "l"(v));
}
// horizontal add of a packed pair -> scalar float
__device__ __forceinline__ float hadd2(ull v) {
    u32 lo, hi; up2(v, lo, hi);
    return __uint_as_float(lo) + __uint_as_float(hi);
}

__global__ void __launch_bounds__(128, 5) gdn_kernel(
    const float* __restrict__ x,  const float* __restrict__ gk,
    const float* __restrict__ gs, const float* __restrict__ beta,
    const float* __restrict__ bo, const float* __restrict__ go,
    float* __restrict__ out)
{
    const int ct  = threadIdx.x;     // channel-thread: channels [2ct, 2ct+2)
    const int cb  = ct * 2;
    const int qid = ct & 3;          // position within 4-thread group quad

    int bi = blockIdx.x;
    const int wp = bi % 28; bi /= 28;   // w-pair: output cols w0, w0+1
    const int hq = bi & 3;  bi >>= 2;
    const int b  = bi;
    const int w0 = wp * 2;
    const int h0 = hq * 14;
    const bool wl = (wp > 0), wr = (wp < 27);

    // ---- Pk weights, TRANSPOSED packing: pair = (w[2src,c], w[2src+1,c]) ----
    // so the thread's (and shuffled) x^2 pairs are consumed AS-IS (no lane dup)
    ull Wt[4][2];
#pragma unroll
    for (int j = 0; j < 4; j++) {
        const int src = qid ^ j;
        const float* g0 = gk + (2 * src)     * Cn + cb;
        const float* g1 = gk + (2 * src + 1) * Cn + cb;
        Wt[j][0] = pk2(__float_as_uint(g0[0]), __float_as_uint(g1[0]));
        Wt[j][1] = pk2(__float_as_uint(g0[1]), __float_as_uint(g1[1]));
    }
    // ---- Ps taps (3x3 minus center) ----
    const int tapi[8] = {0, 1, 2, 3, 5, 6, 7, 8};
    ull kp[8];
#pragma unroll
    for (int t = 0; t < 8; t++)
        kp[t] = *(const ull*)(gs + tapi[t] * Cn + cb);

    float2 bt = *(const float2*)(beta + cb);
    const ull bp  = pk2(__float_as_uint(bt.x + 1e-6f), __float_as_uint(bt.y + 1e-6f));
    const ull gov = *(const ull*)(go + cb);
    const ull bov = *(const ull*)(bo + cb);

    const float* xw = x   + (((size_t)b * Hn) * Wn + w0) * Cn + cb;
    float*       ob = out + (((size_t)b * Hn) * Wn + w0) * Cn + cb;

    // load 4 raw columns (w0-1, w0, w0+1, w0+2) of row hg
    auto ldrow = [&](int hg, ull &L, ull &C0, ull &C1, ull &R) {
        L = 0; C0 = 0; C1 = 0; R = 0;
        if (hg >= 0 && hg < Hn) {
            const float* p = xw + (size_t)hg * RS;
            if (wl) L = *(const ull*)(p - Cn);
            C0 = *(const ull*)(p);
            C1 = *(const ull*)(p + Cn);
            if (wr) R = *(const ull*)(p + 2 * Cn);
        }
    };

    // squared window rows a(h-1), b(h), c(h+1) x cols (w0-1, w0, w0+1, w0+2)
    ull aSL, aS0, aS1, aSR, bSL, bS0, bS1, bSR, cSL, cS0, cS1, cSR;
    ull rb0, rb1, rc0, rc1;          // raw center cols for rows h (out) and h+1
    ull p1L, p1C0, p1C1, p1R;        // raw prefetch row h+2
    ull p2L, p2C0, p2C1, p2R;        // raw prefetch row h+3

    {
        ull L, C0, C1, R;
        ldrow(h0 - 1, L, C0, C1, R);
        aSL = mul2(L, L); aS0 = mul2(C0, C0); aS1 = mul2(C1, C1); aSR = mul2(R, R);
        ldrow(h0, L, C0, C1, R);
        bSL = mul2(L, L); bS0 = mul2(C0, C0); bS1 = mul2(C1, C1); bSR = mul2(R, R);
        rb0 = C0; rb1 = C1;
        ldrow(h0 + 1, L, C0, C1, R);
        cSL = mul2(L, L); cS0 = mul2(C0, C0); cS1 = mul2(C1, C1); cSR = mul2(R, R);
        rc0 = C0; rc1 = C1;
        ldrow(h0 + 2, p1L, p1C0, p1C1, p1R);
        ldrow(h0 + 3, p2L, p2C0, p2C1, p2R);
    }

#pragma unroll
    for (int s = 0; s < 14; s++) {
        const int h = h0 + s;

        // ---- Pk inputs: independent butterflies off both center x^2 cols ----
        const ull v0b = __shfl_xor_sync(0xffffffffu, bS0, 1);
        const ull v0c = __shfl_xor_sync(0xffffffffu, bS0, 2);
        const ull v0d = __shfl_xor_sync(0xffffffffu, bS0, 3);
        const ull v1b = __shfl_xor_sync(0xffffffffu, bS1, 1);
        const ull v1c = __shfl_xor_sync(0xffffffffu, bS1, 2);
        const ull v1d = __shfl_xor_sync(0xffffffffu, bS1, 3);

        // ---- col w0: Pk, lane-split partial sums (no lane broadcasts) ----
        ull P0 = mul2(bS0, Wt[0][0]);
        ull P1 = mul2(bS0, Wt[0][1]);
        P0 = fma2(v0b, Wt[1][0], P0);  P1 = fma2(v0b, Wt[1][1], P1);
        P0 = fma2(v0c, Wt[2][0], P0);  P1 = fma2(v0c, Wt[2][1], P1);
        P0 = fma2(v0d, Wt[3][0], P0);  P1 = fma2(v0d, Wt[3][1], P1);
        const ull pkp0 = pk2(__float_as_uint(hadd2(P0)), __float_as_uint(hadd2(P1)));
        // ---- col w0: Ps (2 chains, one seeded with beta+BETA_MIN) ----
        ull C0a = fma2(aSL, kp[0], bp);
        ull D0a = mul2(aS0, kp[1]);
        C0a = fma2(aS1, kp[2], C0a);
        D0a = fma2(bSL, kp[3], D0a);
        C0a = fma2(bS1, kp[4], C0a);
        D0a = fma2(cSL, kp[5], D0a);
        C0a = fma2(cS0, kp[6], C0a);
        D0a = fma2(cS1, kp[7], D0a);
        const ull acc0 = add2(pkp0, add2(C0a, D0a));

        // ---- col w0+1: Pk ----
        ull Q0 = mul2(bS1, Wt[0][0]);
        ull Q1 = mul2(bS1, Wt[0][1]);
        Q0 = fma2(v1b, Wt[1][0], Q0);  Q1 = fma2(v1b, Wt[1][1], Q1);
        Q0 = fma2(v1c, Wt[2][0], Q0);  Q1 = fma2(v1c, Wt[2][1], Q1);
        Q0 = fma2(v1d, Wt[3][0], Q0);  Q1 = fma2(v1d, Wt[3][1], Q1);
        const ull pkp1 = pk2(__float_as_uint(hadd2(Q0)), __float_as_uint(hadd2(Q1)));
        // ---- col w0+1: Ps ----
        ull C1a = fma2(aS0, kp[0], bp);
        ull D1a = mul2(aS1, kp[1]);
        C1a = fma2(aSR, kp[2], C1a);
        D1a = fma2(bS0, kp[3], D1a);
        C1a = fma2(bSR, kp[4], C1a);
        D1a = fma2(cS0, kp[5], D1a);
        C1a = fma2(cS1, kp[6], C1a);
        D1a = fma2(cSR, kp[7], D1a);
        const ull acc1 = add2(pkp1, add2(C1a, D1a));

        // ---- epilogue: x * rsqrt(acc) * gamma_o + beta_o (both cols) ----
        u32 a0, a1;
        float* po = ob + (size_t)h * RS;
        up2(acc0, a0, a1);
        {
            const float r0 = rsqrtf(__uint_as_float(a0));
            const float r1 = rsqrtf(__uint_as_float(a1));
            const ull rp = pk2(__float_as_uint(r0), __float_as_uint(r1));
            *(ull*)(po) = fma2(mul2(rb0, rp), gov, bov);
        }
        up2(acc1, a0, a1);
        {
            const float r0 = rsqrtf(__uint_as_float(a0));
            const float r1 = rsqrtf(__uint_as_float(a1));
            const ull rp = pk2(__float_as_uint(r0), __float_as_uint(r1));
            *(ull*)(po + Cn) = fma2(mul2(rb1, rp), gov, bov);
        }

        // ---- shift window; absorb prefetch row 1; rotate; issue new load ----
        aSL = bSL; aS0 = bS0; aS1 = bS1; aSR = bSR;
        bSL = cSL; bS0 = cS0; bS1 = cS1; bSR = cSR;
        cSL = mul2(p1L, p1L);  cS0 = mul2(p1C0, p1C0);
        cS1 = mul2(p1C1, p1C1); cSR = mul2(p1R, p1R);
        rb0 = rc0; rb1 = rc1;
        rc0 = p1C0; rc1 = p1C1;
        p1L = p2L; p1C0 = p2C0; p1C1 = p2C1; p1R = p2R;
        ldrow(h + 4, p2L, p2C0, p2C1, p2R);
    }
}

extern "C" void kernel_launch(void* const* d_in, const int* in_sizes, int n_in,
                              void* d_out, int out_size) {
    const float* x    = (const float*)d_in[0];
    const float* gk   = (const float*)d_in[1];
    const float* gs   = (const float*)d_in[2];
    const float* beta = (const float*)d_in[3];
    const float* bo   = (const float*)d_in[4];
    const float* go   = (const float*)d_in[5];
    gdn_kernel<<<Bn * 4 * 28, 128>>>(x, gk, gs, beta, bo, go, (float*)d_out);
}

// round 8
// speedup vs baseline: 1.2342x; 1.2342x over previous
#include <cuda_runtime.h>
#include <cstdint>

#define Bn 32
#define Hn 56
#define Wn 56
#define Cn 256
#define RS (Wn * Cn)

typedef unsigned long long ull;
typedef unsigned int u32;

// ---- packed f32x2 helpers (Blackwell FFMA2 path: only reachable via PTX) ----
__device__ __forceinline__ ull fma2(ull a, ull b, ull c) {
    ull d; asm("fma.rn.f32x2 %0, %1, %2, %3;" : "=l"(d) : "l"(a), "l"(b), "l"(c)); return d;
}
__device__ __forceinline__ ull mul2(ull a, ull b) {
    ull d; asm("mul.rn.f32x2 %0, %1, %2;" : "=l"(d) : "l"(a), "l"(b)); return d;
}
__device__ __forceinline__ ull add2(ull a, ull b) {
    ull d; asm("add.rn.f32x2 %0, %1, %2;" : "=l"(d) : "l"(a), "l"(b)); return d;
}
__device__ __forceinline__ ull pk2(u32 lo, u32 hi) {
    ull d; asm("mov.b64 %0, {%1, %2};" : "=l"(d) : "r"(lo), "r"(hi)); return d;
}
__device__ __forceinline__ ull dup2(u32 v) {
    ull d; asm("mov.b64 %0, {%1, %1};" : "=l"(d) : "r"(v)); return d;
}
__device__ __forceinline__ void up2(ull v, u32 &lo, u32 &hi) {
    asm("mov.b64 {%0, %1}, %2;" : "=r"(lo), "=r"(hi) : "l"(v));
}

__global__ void __launch_bounds__(128, 5) gdn_kernel(
    const float* __restrict__ x,  const float* __restrict__ gk,
    const float* __restrict__ gs, const float* __restrict__ beta,
    const float* __restrict__ bo, const float* __restrict__ go,
    float* __restrict__ out)
{
    const int ct  = threadIdx.x;     // channel-thread: channels [2ct, 2ct+2)
    const int cb  = ct * 2;
    const int qid = ct & 3;          // position within 4-thread group quad

    int bi = blockIdx.x;
    const int wp = bi % 28; bi /= 28;   // w-pair: output cols w0, w0+1
    const int hq = bi & 3;  bi >>= 2;
    const int b  = bi;
    const int w0 = wp * 2;
    const int h0 = hq * 14;
    const bool wl = (wp > 0), wr = (wp < 27);

    // ---- Pk weights, pre-permuted into shuffle-delivery order (R5 scheme) ----
    ull Wp[8];
#pragma unroll
    for (int j = 0; j < 4; j++) {
        const int src = qid ^ j;
        Wp[2 * j]     = *(const ull*)(gk + (2 * src)     * Cn + cb);
        Wp[2 * j + 1] = *(const ull*)(gk + (2 * src + 1) * Cn + cb);
    }
    // ---- Ps taps (3x3 minus center) ----
    const int tapi[8] = {0, 1, 2, 3, 5, 6, 7, 8};
    ull kp[8];
#pragma unroll
    for (int t = 0; t < 8; t++)
        kp[t] = *(const ull*)(gs + tapi[t] * Cn + cb);

    float2 bt = *(const float2*)(beta + cb);
    const ull bp  = pk2(__float_as_uint(bt.x + 1e-6f), __float_as_uint(bt.y + 1e-6f));
    const ull gov = *(const ull*)(go + cb);
    const ull bov = *(const ull*)(bo + cb);

    const float* xw = x   + (((size_t)b * Hn) * Wn + w0) * Cn + cb;
    float*       ob = out + (((size_t)b * Hn) * Wn + w0) * Cn + cb;

    // window: 4 rows (r0-1 .. r0+2) x 4 cols. Halos (L,R) squared once absorbed;
    // centers (c0,c1) kept RAW (epilogue needs raw; squares recomputed per iter).
    ull wL[4], wc0[4], wc1[4], wR[4];

    // raw load of one row's 4 columns (no h check; w halos predicated)
    auto ldraw = [&](int hg, ull &L, ull &C0, ull &C1, ull &R) {
        const float* p = xw + (size_t)hg * RS;
        L = 0; R = 0;
        if (wl) L = *(const ull*)(p - Cn);
        C0 = *(const ull*)(p);
        C1 = *(const ull*)(p + Cn);
        if (wr) R = *(const ull*)(p + 2 * Cn);
    };

    // ---- fill: rows h0-1..h0+2 -> slots 0..3; square halos of slots 0,1 only ----
    if (h0 > 0) ldraw(h0 - 1, wL[0], wc0[0], wc1[0], wR[0]);
    else { wL[0] = 0; wc0[0] = 0; wc1[0] = 0; wR[0] = 0; }
    ldraw(h0,     wL[1], wc0[1], wc1[1], wR[1]);
    ldraw(h0 + 1, wL[2], wc0[2], wc1[2], wR[2]);
    ldraw(h0 + 2, wL[3], wc0[3], wc1[3], wR[3]);
    wL[0] = mul2(wL[0], wL[0]); wR[0] = mul2(wR[0], wR[0]);
    wL[1] = mul2(wL[1], wL[1]); wR[1] = mul2(wR[1], wR[1]);

    // ---- main body: 7 iterations x 2 output rows; hchk folds at inline time ----
    auto body = [&](bool hchk) {
#pragma unroll
        for (int k = 0; k < 7; k++) {
            const int r0 = h0 + 2 * k;

            // square newly-arrived halos (slots 2,3)
            wL[2] = mul2(wL[2], wL[2]); wR[2] = mul2(wR[2], wR[2]);
            wL[3] = mul2(wL[3], wL[3]); wR[3] = mul2(wR[3], wR[3]);

            // center squares for all 4 rows
            const ull s00 = mul2(wc0[0], wc0[0]), s10 = mul2(wc1[0], wc1[0]);
            const ull s01 = mul2(wc0[1], wc0[1]), s11 = mul2(wc1[1], wc1[1]);
            const ull s02 = mul2(wc0[2], wc0[2]), s12 = mul2(wc1[2], wc1[2]);
            const ull s03 = mul2(wc0[3], wc0[3]), s13 = mul2(wc1[3], wc1[3]);

            // ---- butterflies for the 2 center rows x 2 cols (12 shfl.64) ----
            const ull A0b = __shfl_xor_sync(0xffffffffu, s01, 1);
            const ull A0c = __shfl_xor_sync(0xffffffffu, s01, 2);
            const ull A0d = __shfl_xor_sync(0xffffffffu, s01, 3);
            const ull A1b = __shfl_xor_sync(0xffffffffu, s11, 1);
            const ull A1c = __shfl_xor_sync(0xffffffffu, s11, 2);
            const ull A1d = __shfl_xor_sync(0xffffffffu, s11, 3);
            const ull B0b = __shfl_xor_sync(0xffffffffu, s02, 1);
            const ull B0c = __shfl_xor_sync(0xffffffffu, s02, 2);
            const ull B0d = __shfl_xor_sync(0xffffffffu, s02, 3);
            const ull B1b = __shfl_xor_sync(0xffffffffu, s12, 1);
            const ull B1c = __shfl_xor_sync(0xffffffffu, s12, 2);
            const ull B1d = __shfl_xor_sync(0xffffffffu, s12, 3);

            u32 t0, t1;
            // ======== output row r0 (center slot 1) ========
            // col c0: Pk
            ull A0 = bp, A0x;
            up2(s01, t0, t1);
            A0  = fma2(dup2(t0), Wp[0], A0);   A0x = mul2(dup2(t1), Wp[1]);
            up2(A0b, t0, t1);
            A0  = fma2(dup2(t0), Wp[2], A0);   A0x = fma2(dup2(t1), Wp[3], A0x);
            up2(A0c, t0, t1);
            A0  = fma2(dup2(t0), Wp[4], A0);   A0x = fma2(dup2(t1), Wp[5], A0x);
            up2(A0d, t0, t1);
            A0  = fma2(dup2(t0), Wp[6], A0);   A0x = fma2(dup2(t1), Wp[7], A0x);
            // col c0: Ps
            ull A0y = mul2(wL[0], kp[0]);
            ull A0z = mul2(s00,   kp[1]);
            A0y = fma2(s10,   kp[2], A0y);
            A0z = fma2(wL[1], kp[3], A0z);
            A0y = fma2(s11,   kp[4], A0y);
            A0z = fma2(wL[2], kp[5], A0z);
            A0y = fma2(s02,   kp[6], A0y);
            A0z = fma2(s12,   kp[7], A0z);
            const ull acc00 = add2(add2(A0, A0x), add2(A0y, A0z));
            // col c1: Pk
            ull A1 = bp, A1x;
            up2(s11, t0, t1);
            A1  = fma2(dup2(t0), Wp[0], A1);   A1x = mul2(dup2(t1), Wp[1]);
            up2(A1b, t0, t1);
            A1  = fma2(dup2(t0), Wp[2], A1);   A1x = fma2(dup2(t1), Wp[3], A1x);
            up2(A1c, t0, t1);
            A1  = fma2(dup2(t0), Wp[4], A1);   A1x = fma2(dup2(t1), Wp[5], A1x);
            up2(A1d, t0, t1);
            A1  = fma2(dup2(t0), Wp[6], A1);   A1x = fma2(dup2(t1), Wp[7], A1x);
            // col c1: Ps
            ull A1y = mul2(s00, kp[0]);
            ull A1z = mul2(s10, kp[1]);
            A1y = fma2(wR[0], kp[2], A1y);
            A1z = fma2(s01,   kp[3], A1z);
            A1y = fma2(wR[1], kp[4], A1y);
            A1z = fma2(s02,   kp[5], A1z);
            A1y = fma2(s12,   kp[6], A1y);
            A1z = fma2(wR[2], kp[7], A1z);
            const ull acc01 = add2(add2(A1, A1x), add2(A1y, A1z));

            // ======== output row r0+1 (center slot 2) ========
            // col c0: Pk
            ull B0 = bp, B0x;
            up2(s02, t0, t1);
            B0  = fma2(dup2(t0), Wp[0], B0);   B0x = mul2(dup2(t1), Wp[1]);
            up2(B0b, t0, t1);
            B0  = fma2(dup2(t0), Wp[2], B0);   B0x = fma2(dup2(t1), Wp[3], B0x);
            up2(B0c, t0, t1);
            B0  = fma2(dup2(t0), Wp[4], B0);   B0x = fma2(dup2(t1), Wp[5], B0x);
            up2(B0d, t0, t1);
            B0  = fma2(dup2(t0), Wp[6], B0);   B0x = fma2(dup2(t1), Wp[7], B0x);
            // col c0: Ps
            ull B0y = mul2(wL[1], kp[0]);
            ull B0z = mul2(s01,   kp[1]);
            B0y = fma2(s11,   kp[2], B0y);
            B0z = fma2(wL[2], kp[3], B0z);
            B0y = fma2(s12,   kp[4], B0y);
            B0z = fma2(wL[3], kp[5], B0z);
            B0y = fma2(s03,   kp[6], B0y);
            B0z = fma2(s13,   kp[7], B0z);
            const ull acc10 = add2(add2(B0, B0x), add2(B0y, B0z));
            // col c1: Pk
            ull B1 = bp, B1x;
            up2(s12, t0, t1);
            B1  = fma2(dup2(t0), Wp[0], B1);   B1x = mul2(dup2(t1), Wp[1]);
            up2(B1b, t0, t1);
            B1  = fma2(dup2(t0), Wp[2], B1);   B1x = fma2(dup2(t1), Wp[3], B1x);
            up2(B1c, t0, t1);
            B1  = fma2(dup2(t0), Wp[4], B1);   B1x = fma2(dup2(t1), Wp[5], B1x);
            up2(B1d, t0, t1);
            B1  = fma2(dup2(t0), Wp[6], B1);   B1x = fma2(dup2(t1), Wp[7], B1x);
            // col c1: Ps
            ull B1y = mul2(s01, kp[0]);
            ull B1z = mul2(s11, kp[1]);
            B1y = fma2(wR[1], kp[2], B1y);
            B1z = fma2(s02,   kp[3], B1z);
            B1y = fma2(wR[2], kp[4], B1y);
            B1z = fma2(s03,   kp[5], B1z);
            B1y = fma2(s13,   kp[6], B1y);
            B1z = fma2(wR[3], kp[7], B1z);
            const ull acc11 = add2(add2(B1, B1x), add2(B1y, B1z));

            // ---- epilogue: x * rsqrt(acc) * gamma_o + beta_o (4 outputs) ----
            float* po = ob + (size_t)r0 * RS;
            u32 a0, a1;
            up2(acc00, a0, a1);
            {
                const ull rp = pk2(__float_as_uint(rsqrtf(__uint_as_float(a0))),
                                   __float_as_uint(rsqrtf(__uint_as_float(a1))));
                *(ull*)(po) = fma2(mul2(wc0[1], rp), gov, bov);
            }
            up2(acc01, a0, a1);
            {
                const ull rp = pk2(__float_as_uint(rsqrtf(__uint_as_float(a0))),
                                   __float_as_uint(rsqrtf(__uint_as_float(a1))));
                *(ull*)(po + Cn) = fma2(mul2(wc1[1], rp), gov, bov);
            }
            up2(acc10, a0, a1);
            {
                const ull rp = pk2(__float_as_uint(rsqrtf(__uint_as_float(a0))),
                                   __float_as_uint(rsqrtf(__uint_as_float(a1))));
                *(ull*)(po + RS) = fma2(mul2(wc0[2], rp), gov, bov);
            }
            up2(acc11, a0, a1);
            {
                const ull rp = pk2(__float_as_uint(rsqrtf(__uint_as_float(a0))),
                                   __float_as_uint(rsqrtf(__uint_as_float(a1))));
                *(ull*)(po + RS + Cn) = fma2(mul2(wc1[2], rp), gov, bov);
            }

            // ---- shift by 2 rows; load next 2 rows straight into slots 2,3 ----
            if (k < 6) {
                wL[0] = wL[2]; wc0[0] = wc0[2]; wc1[0] = wc1[2]; wR[0] = wR[2];
                wL[1] = wL[3]; wc0[1] = wc0[3]; wc1[1] = wc1[3]; wR[1] = wR[3];
                const int rn0 = r0 + 3, rn1 = r0 + 4;
                if (!hchk || rn0 < Hn) ldraw(rn0, wL[2], wc0[2], wc1[2], wR[2]);
                else { wL[2] = 0; wc0[2] = 0; wc1[2] = 0; wR[2] = 0; }
                if (!hchk || rn1 < Hn) ldraw(rn1, wL[3], wc0[3], wc1[3], wR[3]);
                else { wL[3] = 0; wc0[3] = 0; wc1[3] = 0; wR[3] = 0; }
            }
        }
    };

    if (h0 != 42) body(false);   // rows touched ≤ h0+16 ≤ 44 < 56: no h checks
    else          body(true);    // last h tile: bounds-checked loads
}

extern "C" void kernel_launch(void* const* d_in, const int* in_sizes, int n_in,
                              void* d_out, int out_size) {
    const float* x    = (const float*)d_in[0];
    const float* gk   = (const float*)d_in[1];
    const float* gs   = (const float*)d_in[2];
    const float* beta = (const float*)d_in[3];
    const float* bo   = (const float*)d_in[4];
    const float* go   = (const float*)d_in[5];
    gdn_kernel<<<Bn * 4 * 28, 128>>>(x, gk, gs, beta, bo, go, (float*)d_out);
}

// round 9
// speedup vs baseline: 1.2899x; 1.0452x over previous
#include <cuda_runtime.h>
#include <cstdint>

#define Bn 32
#define Hn 56
#define Wn 56
#define Cn 256
#define RS (Wn * Cn)
#define NTILES (Bn * 4 * 28)
#define NBLK   760              // 152 SMs x 5 resident blocks

typedef unsigned long long ull;
typedef unsigned int u32;

// ---- packed f32x2 helpers (Blackwell FFMA2 path: only reachable via PTX) ----
__device__ __forceinline__ ull fma2(ull a, ull b, ull c) {
    ull d; asm("fma.rn.f32x2 %0, %1, %2, %3;" : "=l"(d) : "l"(a), "l"(b), "l"(c)); return d;
}
__device__ __forceinline__ ull mul2(ull a, ull b) {
    ull d; asm("mul.rn.f32x2 %0, %1, %2;" : "=l"(d) : "l"(a), "l"(b)); return d;
}
__device__ __forceinline__ ull add2(ull a, ull b) {
    ull d; asm("add.rn.f32x2 %0, %1, %2;" : "=l"(d) : "l"(a), "l"(b)); return d;
}
__device__ __forceinline__ ull pk2(u32 lo, u32 hi) {
    ull d; asm("mov.b64 %0, {%1, %2};" : "=l"(d) : "r"(lo), "r"(hi)); return d;
}
__device__ __forceinline__ ull dup2(u32 v) {
    ull d; asm("mov.b64 %0, {%1, %1};" : "=l"(d) : "r"(v)); return d;
}
__device__ __forceinline__ void up2(ull v, u32 &lo, u32 &hi) {
    asm("mov.b64 {%0, %1}, %2;" : "=r"(lo), "=r"(hi) : "l"(v));
}

__global__ void __launch_bounds__(128, 5) gdn_kernel(
    const float* __restrict__ x,  const float* __restrict__ gk,
    const float* __restrict__ gs, const float* __restrict__ beta,
    const float* __restrict__ bo, const float* __restrict__ go,
    float* __restrict__ out)
{
    const int ct  = threadIdx.x;     // channel-thread: channels [2ct, 2ct+2)
    const int cb  = ct * 2;
    const int qid = ct & 3;          // position within 4-thread group quad

    // ======== tile-invariant state: loaded ONCE per persistent block ========
    ull Wp[8];                       // Pk weights, pre-permuted to shuffle order
#pragma unroll
    for (int j = 0; j < 4; j++) {
        const int src = qid ^ j;
        Wp[2 * j]     = *(const ull*)(gk + (2 * src)     * Cn + cb);
        Wp[2 * j + 1] = *(const ull*)(gk + (2 * src + 1) * Cn + cb);
    }
    const int tapi[8] = {0, 1, 2, 3, 5, 6, 7, 8};   // 3x3 minus center
    ull kp[8];
#pragma unroll
    for (int t = 0; t < 8; t++)
        kp[t] = *(const ull*)(gs + tapi[t] * Cn + cb);

    float2 bt = *(const float2*)(beta + cb);
    const ull bp  = pk2(__float_as_uint(bt.x + 1e-6f), __float_as_uint(bt.y + 1e-6f));
    const ull gov = *(const ull*)(go + cb);
    const ull bov = *(const ull*)(bo + cb);

    // ======== persistent loop over tiles ========
    for (int tile = blockIdx.x; tile < NTILES; tile += NBLK) {
        int bi = tile;
        const int wp = bi % 28; bi /= 28;   // w-pair: output cols w0, w0+1
        const int hq = bi & 3;  bi >>= 2;
        const int b  = bi;
        const int w0 = wp * 2;
        const int h0 = hq * 14;
        const bool wl = (wp > 0), wr = (wp < 27);

        const float* xw = x   + (((size_t)b * Hn) * Wn + w0) * Cn + cb;
        float*       ob = out + (((size_t)b * Hn) * Wn + w0) * Cn + cb;

        // load 4 raw columns (w0-1, w0, w0+1, w0+2) of row hg
        auto ldrow = [&](int hg, ull &L, ull &C0, ull &C1, ull &R) {
            L = 0; C0 = 0; C1 = 0; R = 0;
            if (hg >= 0 && hg < Hn) {
                const float* p = xw + (size_t)hg * RS;
                if (wl) L = *(const ull*)(p - Cn);
                C0 = *(const ull*)(p);
                C1 = *(const ull*)(p + Cn);
                if (wr) R = *(const ull*)(p + 2 * Cn);
            }
        };

        // squared window rows a(h-1), b(h), c(h+1) x cols (w0-1..w0+2)
        ull aSL, aS0, aS1, aSR, bSL, bS0, bS1, bSR, cSL, cS0, cS1, cSR;
        ull rb0, rb1, rc0, rc1;          // raw center cols rows h, h+1
        ull p1L, p1C0, p1C1, p1R;        // raw prefetch row h+2
        ull p2L, p2C0, p2C1, p2R;        // raw prefetch row h+3

        {
            ull L, C0, C1, R;
            ldrow(h0 - 1, L, C0, C1, R);
            aSL = mul2(L, L); aS0 = mul2(C0, C0); aS1 = mul2(C1, C1); aSR = mul2(R, R);
            ldrow(h0, L, C0, C1, R);
            bSL = mul2(L, L); bS0 = mul2(C0, C0); bS1 = mul2(C1, C1); bSR = mul2(R, R);
            rb0 = C0; rb1 = C1;
            ldrow(h0 + 1, L, C0, C1, R);
            cSL = mul2(L, L); cS0 = mul2(C0, C0); cS1 = mul2(C1, C1); cSR = mul2(R, R);
            rc0 = C0; rc1 = C1;
            ldrow(h0 + 2, p1L, p1C0, p1C1, p1R);
            ldrow(h0 + 3, p2L, p2C0, p2C1, p2R);
        }

#pragma unroll
        for (int s = 0; s < 14; s++) {
            const int h = h0 + s;

            // ---- Pk inputs: independent butterflies off both center cols ----
            const ull v0b = __shfl_xor_sync(0xffffffffu, bS0, 1);
            const ull v0c = __shfl_xor_sync(0xffffffffu, bS0, 2);
            const ull v0d = __shfl_xor_sync(0xffffffffu, bS0, 3);
            const ull v1b = __shfl_xor_sync(0xffffffffu, bS1, 1);
            const ull v1c = __shfl_xor_sync(0xffffffffu, bS1, 2);
            const ull v1d = __shfl_xor_sync(0xffffffffu, bS1, 3);

            u32 s0, s1;
            // ---- col w0: Pk (2 chains) ----
            ull A0 = bp, B0;
            up2(bS0, s0, s1);
            A0 = fma2(dup2(s0), Wp[0], A0);  B0 = mul2(dup2(s1), Wp[1]);
            up2(v0b, s0, s1);
            A0 = fma2(dup2(s0), Wp[2], A0);  B0 = fma2(dup2(s1), Wp[3], B0);
            up2(v0c, s0, s1);
            A0 = fma2(dup2(s0), Wp[4], A0);  B0 = fma2(dup2(s1), Wp[5], B0);
            up2(v0d, s0, s1);
            A0 = fma2(dup2(s0), Wp[6], A0);  B0 = fma2(dup2(s1), Wp[7], B0);
            // ---- col w0: Ps (2 chains) ----
            ull C0a = mul2(aSL, kp[0]);
            ull D0a = mul2(aS0, kp[1]);
            C0a = fma2(aS1, kp[2], C0a);
            D0a = fma2(bSL, kp[3], D0a);
            C0a = fma2(bS1, kp[4], C0a);
            D0a = fma2(cSL, kp[5], D0a);
            C0a = fma2(cS0, kp[6], C0a);
            D0a = fma2(cS1, kp[7], D0a);
            const ull acc0 = add2(add2(A0, B0), add2(C0a, D0a));

            // ---- col w0+1: Pk ----
            ull A1 = bp, B1;
            up2(bS1, s0, s1);
            A1 = fma2(dup2(s0), Wp[0], A1);  B1 = mul2(dup2(s1), Wp[1]);
            up2(v1b, s0, s1);
            A1 = fma2(dup2(s0), Wp[2], A1);  B1 = fma2(dup2(s1), Wp[3], B1);
            up2(v1c, s0, s1);
            A1 = fma2(dup2(s0), Wp[4], A1);  B1 = fma2(dup2(s1), Wp[5], B1);
            up2(v1d, s0, s1);
            A1 = fma2(dup2(s0), Wp[6], A1);  B1 = fma2(dup2(s1), Wp[7], B1);
            // ---- col w0+1: Ps ----
            ull C1a = mul2(aS0, kp[0]);
            ull D1a = mul2(aS1, kp[1]);
            C1a = fma2(aSR, kp[2], C1a);
            D1a = fma2(bS0, kp[3], D1a);
            C1a = fma2(bSR, kp[4], C1a);
            D1a = fma2(cS0, kp[5], D1a);
            C1a = fma2(cS1, kp[6], C1a);
            D1a = fma2(cSR, kp[7], D1a);
            const ull acc1 = add2(add2(A1, B1), add2(C1a, D1a));

            // ---- epilogue: x * rsqrt(acc) * gamma_o + beta_o (both cols) ----
            u32 a0, a1;
            float* po = ob + (size_t)h * RS;
            up2(acc0, a0, a1);
            {
                const float r0 = rsqrtf(__uint_as_float(a0));
                const float r1 = rsqrtf(__uint_as_float(a1));
                const ull rp = pk2(__float_as_uint(r0), __float_as_uint(r1));
                *(ull*)(po) = fma2(mul2(rb0, rp), gov, bov);
            }
            up2(acc1, a0, a1);
            {
                const float r0 = rsqrtf(__uint_as_float(a0));
                const float r1 = rsqrtf(__uint_as_float(a1));
                const ull rp = pk2(__float_as_uint(r0), __float_as_uint(r1));
                *(ull*)(po + Cn) = fma2(mul2(rb1, rp), gov, bov);
            }

            // ---- shift window; absorb prefetch row 1 (needed through s=12) ----
            if (s < 13) {
                aSL = bSL; aS0 = bS0; aS1 = bS1; aSR = bSR;
                bSL = cSL; bS0 = cS0; bS1 = cS1; bSR = cSR;
                cSL = mul2(p1L, p1L);  cS0 = mul2(p1C0, p1C0);
                cS1 = mul2(p1C1, p1C1); cSR = mul2(p1R, p1R);
                rb0 = rc0; rb1 = rc1;
                rc0 = p1C0; rc1 = p1C1;
                p1L = p2L; p1C0 = p2C0; p1C1 = p2C1; p1R = p2R;
                // last consumed row is h0+14, loaded at s=10 -> no loads after
                if (s < 11) ldrow(h + 4, p2L, p2C0, p2C1, p2R);
            }
        }
    }
}

extern "C" void kernel_launch(void* const* d_in, const int* in_sizes, int n_in,
                              void* d_out, int out_size) {
    const float* x    = (const float*)d_in[0];
    const float* gk   = (const float*)d_in[1];
    const float* gs   = (const float*)d_in[2];
    const float* beta = (const float*)d_in[3];
    const float* bo   = (const float*)d_in[4];
    const float* go   = (const float*)d_in[5];
    gdn_kernel<<<NBLK, 128>>>(x, gk, gs, beta, bo, go, (float*)d_out);
}